// round 9
// baseline (speedup 1.0000x reference)
#include <cuda_runtime.h>
#include <cuda_bf16.h>
#include <cuda_fp16.h>
#include <cstdint>

#define NUM_USERS 100000
#define NUM_ITEMS 50000
#define N_NODES   150000
#define EMB_DIM   64
#define TEXT_DIM  384
#define N64 (N_NODES * EMB_DIM)
#define N32 (N_NODES * 32)        // fp16 words per stream buffer
#define MAX_EDGES 5000000

// fp32 text projection (exact, used in fusion sums)
__device__ float g_text0[N64];

// Deinterleaved fp16 buffers: per node 32 uint words (64 halves = one stream).
__device__ unsigned g_id0h[N32];
__device__ unsigned g_tx0h[N32];
__device__ unsigned g_id1h[N32];
__device__ unsigned g_tx1h[N32];
__device__ unsigned g_id2h[N32];
__device__ unsigned g_tx2h[N32];

// CSR machinery
__device__ int  g_cnt[N_NODES];
__device__ int  g_ofs[N_NODES + 1];
__device__ int  g_cur[N_NODES];
__device__ int2 g_edges[MAX_EDGES];   // (col, val bits), row-sorted

static __device__ __forceinline__ unsigned pack_h2(float a, float b) {
    __half2 h = __floats2half2_rn(a, b);
    return *reinterpret_cast<unsigned*>(&h);
}
static __device__ __forceinline__ float2 unpack_h2(unsigned w) {
    return __half22float2(*reinterpret_cast<__half2*>(&w));
}

// ---------------------------------------------------------------------------
// Prep (main stream): fp16 id words from concat(uemb,iemb).
// Thread i: float4 i of flattened concat -> words 2i, 2i+1 of g_id0h.
// ---------------------------------------------------------------------------
__global__ void prep_kernel(const float* __restrict__ uemb,
                            const float* __restrict__ iemb) {
    int i = blockIdx.x * blockDim.x + threadIdx.x;
    const int n4 = N64 / 4;
    const int u4 = NUM_USERS * (EMB_DIM / 4);
    if (i < n4) {
        float4 src = (i < u4) ? ((const float4*)uemb)[i]
                              : ((const float4*)iemb)[i - u4];
        g_id0h[2 * i]     = pack_h2(src.x, src.y);
        g_id0h[2 * i + 1] = pack_h2(src.z, src.w);
    }
}

// ---------------------------------------------------------------------------
// CSR build (side stream): zero counts, histogram, scan, scatter
// ---------------------------------------------------------------------------
__global__ void zero_cnt_kernel() {
    int i = blockIdx.x * blockDim.x + threadIdx.x;
    if (i < N_NODES / 4)
        ((int4*)g_cnt)[i] = make_int4(0, 0, 0, 0);
}

__global__ void hist_kernel(const int* __restrict__ erow, int n_edges) {
    int i = blockIdx.x * blockDim.x + threadIdx.x;
    if (i < n_edges) atomicAdd(&g_cnt[__ldg(erow + i)], 1);
}

__global__ __launch_bounds__(1024)
void scan_kernel() {
    __shared__ int sdata[1024];
    const int t = threadIdx.x;
    const int CHUNK = (N_NODES + 1023) / 1024;   // 147
    int begin = t * CHUNK;
    int end   = begin + CHUNK; if (end > N_NODES) end = N_NODES;
    int s = 0;
    for (int i = begin; i < end; i++) s += g_cnt[i];
    sdata[t] = s;
    __syncthreads();
    for (int off = 1; off < 1024; off <<= 1) {
        int v = (t >= off) ? sdata[t - off] : 0;
        __syncthreads();
        sdata[t] += v;
        __syncthreads();
    }
    int run = sdata[t] - s;
    for (int i = begin; i < end; i++) {
        int c = g_cnt[i];
        g_ofs[i] = run;
        g_cur[i] = run;
        run += c;
    }
    if (t == 1023) g_ofs[N_NODES] = sdata[1023];
}

__global__ void scatter_kernel(const int*   __restrict__ erow,
                               const int*   __restrict__ ecol,
                               const float* __restrict__ eval,
                               int n_edges) {
    int base = (blockIdx.x * blockDim.x + threadIdx.x) * 4;
    #pragma unroll
    for (int j = 0; j < 4; j++) {
        int i = base + j;
        if (i < n_edges) {
            int r = __ldg(erow + i);
            int pos = atomicAdd(&g_cur[r], 1);
            g_edges[pos] = make_int2(__ldg(ecol + i),
                                     __float_as_int(__ldg(eval + i)));
        }
    }
}

// ---------------------------------------------------------------------------
// Text GEMM (packed f32x2 FFMA). Writes fp32 g_text0 + fp16 g_tx0h.
// ---------------------------------------------------------------------------
__global__ void gemm_text_kernel(const float* __restrict__ A,
                                 const float* __restrict__ W,
                                 const float* __restrict__ bias) {
    __shared__ float As[16][132];
    __shared__ float Bs[16][64];

    const int tid = threadIdx.x;
    const int m0  = blockIdx.x * 128;
    const int tr  = tid >> 4;
    const int tc  = tid & 15;

    unsigned long long acc2[4][4];
    #pragma unroll
    for (int ip = 0; ip < 4; ip++)
        #pragma unroll
        for (int j = 0; j < 4; j++) acc2[ip][j] = 0ull;

    for (int k0 = 0; k0 < TEXT_DIM; k0 += 16) {
        #pragma unroll
        for (int p = 0; p < 2; p++) {
            int idx = tid + p * 256;
            int m   = idx >> 2;
            int kq  = idx & 3;
            float4 a4 = make_float4(0.f, 0.f, 0.f, 0.f);
            int gm = m0 + m;
            if (gm < N_NODES)
                a4 = *(const float4*)(A + (size_t)gm * TEXT_DIM + k0 + kq * 4);
            As[kq * 4 + 0][m] = a4.x;
            As[kq * 4 + 1][m] = a4.y;
            As[kq * 4 + 2][m] = a4.z;
            As[kq * 4 + 3][m] = a4.w;
        }
        {
            int k  = tid >> 4;
            int nq = tid & 15;
            float4 b4 = *(const float4*)(W + (size_t)(k0 + k) * 64 + nq * 4);
            *(float4*)&Bs[k][nq * 4] = b4;
        }
        __syncthreads();

        #pragma unroll
        for (int k = 0; k < 16; k++) {
            const unsigned long long* pa =
                (const unsigned long long*)&As[k][tr * 8];
            unsigned long long av[4] = {pa[0], pa[1], pa[2], pa[3]};
            float4 b = *(const float4*)&Bs[k][tc * 4];
            unsigned long long bd[4];
            asm("mov.b64 %0, {%1, %1};" : "=l"(bd[0]) : "r"(__float_as_uint(b.x)));
            asm("mov.b64 %0, {%1, %1};" : "=l"(bd[1]) : "r"(__float_as_uint(b.y)));
            asm("mov.b64 %0, {%1, %1};" : "=l"(bd[2]) : "r"(__float_as_uint(b.z)));
            asm("mov.b64 %0, {%1, %1};" : "=l"(bd[3]) : "r"(__float_as_uint(b.w)));
            #pragma unroll
            for (int ip = 0; ip < 4; ip++)
                #pragma unroll
                for (int j = 0; j < 4; j++)
                    asm("fma.rn.f32x2 %0, %1, %2, %3;"
                        : "=l"(acc2[ip][j])
                        : "l"(av[ip]), "l"(bd[j]), "l"(acc2[ip][j]));
        }
        __syncthreads();
    }

    float4 bv = *(const float4*)(bias + tc * 4);
    #pragma unroll
    for (int ip = 0; ip < 4; ip++) {
        float2 lo_hi[4];
        #pragma unroll
        for (int j = 0; j < 4; j++)
            lo_hi[j] = *reinterpret_cast<float2*>(&acc2[ip][j]);
        #pragma unroll
        for (int half = 0; half < 2; half++) {
            int gm = m0 + tr * 8 + 2 * ip + half;
            if (gm < N_NODES) {
                float4 o;
                o.x = (half ? lo_hi[0].y : lo_hi[0].x) + bv.x;
                o.y = (half ? lo_hi[1].y : lo_hi[1].x) + bv.y;
                o.z = (half ? lo_hi[2].y : lo_hi[2].x) + bv.z;
                o.w = (half ? lo_hi[3].y : lo_hi[3].x) + bv.w;
                *(float4*)(g_text0 + (size_t)gm * 64 + tc * 4) = o;
                g_tx0h[(size_t)gm * 32 + 2 * tc]     = pack_h2(o.x, o.y);
                g_tx0h[(size_t)gm * 32 + 2 * tc + 1] = pack_h2(o.z, o.w);
            }
        }
    }
}

// ---------------------------------------------------------------------------
// Single-stream CSR SpMM: warp per row, half-warps take even/odd edges,
// per lane uint2 gather (16 lanes cover one 128B node vector = 1 line),
// 4 edges in flight per half-warp (8/warp), equal trip counts, shfl combine.
// ---------------------------------------------------------------------------
__global__ void spmm_half_kernel(const unsigned* __restrict__ src,
                                 unsigned* __restrict__ dst) {
    int row  = (blockIdx.x * blockDim.x + threadIdx.x) >> 5;
    int lane = threadIdx.x & 31;
    if (row >= N_NODES) return;

    const int h = lane >> 4;       // edge parity
    const int l = lane & 15;       // uint2 index within node vector

    int beg = __ldg(&g_ofs[row]);
    int end = __ldg(&g_ofs[row + 1]);
    int cnt = end - beg;
    int nfull = cnt >> 3;          // main iterations (8 edges each)

    const uint2* s2 = (const uint2*)src;   // node*16 + l

    float2 a0 = make_float2(0.f, 0.f);
    float2 a1 = make_float2(0.f, 0.f);

    int e = beg + h;
    for (int it = 0; it < nfull; it++, e += 8) {
        int2 d0 = __ldg(&g_edges[e]);
        int2 d1 = __ldg(&g_edges[e + 2]);
        int2 d2 = __ldg(&g_edges[e + 4]);
        int2 d3 = __ldg(&g_edges[e + 6]);
        uint2 w0 = __ldg(s2 + (size_t)d0.x * 16 + l);
        uint2 w1 = __ldg(s2 + (size_t)d1.x * 16 + l);
        uint2 w2 = __ldg(s2 + (size_t)d2.x * 16 + l);
        uint2 w3 = __ldg(s2 + (size_t)d3.x * 16 + l);
        float v0 = __int_as_float(d0.y);
        float v1 = __int_as_float(d1.y);
        float v2 = __int_as_float(d2.y);
        float v3 = __int_as_float(d3.y);
        float2 f;
        f = unpack_h2(w0.x); a0.x += f.x * v0; a0.y += f.y * v0;
        f = unpack_h2(w0.y); a1.x += f.x * v0; a1.y += f.y * v0;
        f = unpack_h2(w1.x); a0.x += f.x * v1; a0.y += f.y * v1;
        f = unpack_h2(w1.y); a1.x += f.x * v1; a1.y += f.y * v1;
        f = unpack_h2(w2.x); a0.x += f.x * v2; a0.y += f.y * v2;
        f = unpack_h2(w2.y); a1.x += f.x * v2; a1.y += f.y * v2;
        f = unpack_h2(w3.x); a0.x += f.x * v3; a0.y += f.y * v3;
        f = unpack_h2(w3.y); a1.x += f.x * v3; a1.y += f.y * v3;
    }
    while (e < end) {              // tail, <= 7 edges total
        int2 d = __ldg(&g_edges[e]);
        uint2 w = __ldg(s2 + (size_t)d.x * 16 + l);
        float v = __int_as_float(d.y);
        float2 f;
        f = unpack_h2(w.x); a0.x += f.x * v; a0.y += f.y * v;
        f = unpack_h2(w.y); a1.x += f.x * v; a1.y += f.y * v;
        e += 2;
    }

    // combine even/odd halves
    a0.x += __shfl_xor_sync(0xffffffffu, a0.x, 16);
    a0.y += __shfl_xor_sync(0xffffffffu, a0.y, 16);
    a1.x += __shfl_xor_sync(0xffffffffu, a1.x, 16);
    a1.y += __shfl_xor_sync(0xffffffffu, a1.y, 16);

    if (h == 0) {
        uint2 w;
        w.x = pack_h2(a0.x, a0.y);
        w.y = pack_h2(a1.x, a1.y);
        ((uint2*)dst)[(size_t)row * 16 + l] = w;
    }
}

// ---------------------------------------------------------------------------
// Fusion as register-blocked GEMM (M=150K, K=128, N=64) + gate epilogue.
// ---------------------------------------------------------------------------
#define FUSE_SMEM (128 * 132 * 4 + 128 * 64 * 4)
__global__ __launch_bounds__(256)
void fuse_gemm_kernel(const float* __restrict__ uemb,
                      const float* __restrict__ iemb,
                      const int*   __restrict__ tail_mask,
                      const float* __restrict__ W_fuse,
                      const float* __restrict__ b_fuse,
                      const float* __restrict__ tail_amp,
                      float* __restrict__ out) {
    extern __shared__ float sm[];
    float* As = sm;                 // [128][132] k-major
    float* Bs = sm + 128 * 132;     // [128][64]

    const int tid = threadIdx.x;
    const int m0  = blockIdx.x * 128;

    #pragma unroll
    for (int p = 0; p < 8; p++) {
        int i = tid + p * 256;
        ((float4*)Bs)[i] = ((const float4*)W_fuse)[i];
    }

    const float amp = 1.f + 1.f / (1.f + __expf(-tail_amp[0]));

    {
        int n    = tid >> 1;
        int node = m0 + n;
        int sub  = tid & 1;
        bool valid = node < N_NODES;
        int nc = valid ? node : 0;
        const float2* id0p = (nc < NUM_USERS)
            ? (const float2*)(uemb + (size_t)nc * 64)
            : (const float2*)(iemb + (size_t)(nc - NUM_USERS) * 64);
        const float2*   t0p  = (const float2*)(g_text0 + (size_t)nc * 64);
        const unsigned* i1p  = g_id1h + (size_t)nc * 32;
        const unsigned* t1p  = g_tx1h + (size_t)nc * 32;
        const unsigned* i2p  = g_id2h + (size_t)nc * 32;
        const unsigned* t2p  = g_tx2h + (size_t)nc * 32;
        const float third = 1.f / 3.f;
        float tmul = (valid && __ldg(tail_mask + nc) != 0) ? amp * third : third;
        #pragma unroll 4
        for (int p = 0; p < 16; p++) {
            int pp = sub * 16 + p;            // dim-pair index 0..31
            float2 i0 = valid ? __ldg(id0p + pp) : make_float2(0.f, 0.f);
            float2 t0 = valid ? __ldg(t0p + pp)  : make_float2(0.f, 0.f);
            float2 l1i = unpack_h2(valid ? __ldg(i1p + pp) : 0u);
            float2 l1t = unpack_h2(valid ? __ldg(t1p + pp) : 0u);
            float2 l2i = unpack_h2(valid ? __ldg(i2p + pp) : 0u);
            float2 l2t = unpack_h2(valid ? __ldg(t2p + pp) : 0u);
            int d = 2 * pp;
            As[(d + 0) * 132 + n]      = (i0.x + l1i.x + l2i.x) * third;
            As[(d + 1) * 132 + n]      = (i0.y + l1i.y + l2i.y) * third;
            As[(64 + d + 0) * 132 + n] = (t0.x + l1t.x + l2t.x) * tmul;
            As[(64 + d + 1) * 132 + n] = (t0.y + l1t.y + l2t.y) * tmul;
        }
    }
    __syncthreads();

    const int tr = tid >> 4;
    const int tc = tid & 15;

    unsigned long long acc2[4][4];
    #pragma unroll
    for (int ip = 0; ip < 4; ip++)
        #pragma unroll
        for (int j = 0; j < 4; j++) acc2[ip][j] = 0ull;

    #pragma unroll 4
    for (int k = 0; k < 128; k++) {
        const unsigned long long* pa =
            (const unsigned long long*)(As + k * 132 + tr * 8);
        unsigned long long av[4] = {pa[0], pa[1], pa[2], pa[3]};
        float4 b = *(const float4*)(Bs + k * 64 + tc * 4);
        unsigned long long bd[4];
        asm("mov.b64 %0, {%1, %1};" : "=l"(bd[0]) : "r"(__float_as_uint(b.x)));
        asm("mov.b64 %0, {%1, %1};" : "=l"(bd[1]) : "r"(__float_as_uint(b.y)));
        asm("mov.b64 %0, {%1, %1};" : "=l"(bd[2]) : "r"(__float_as_uint(b.z)));
        asm("mov.b64 %0, {%1, %1};" : "=l"(bd[3]) : "r"(__float_as_uint(b.w)));
        #pragma unroll
        for (int ip = 0; ip < 4; ip++)
            #pragma unroll
            for (int j = 0; j < 4; j++)
                asm("fma.rn.f32x2 %0, %1, %2, %3;"
                    : "=l"(acc2[ip][j])
                    : "l"(av[ip]), "l"(bd[j]), "l"(acc2[ip][j]));
    }

    float4 bv = *(const float4*)(b_fuse + tc * 4);
    #pragma unroll
    for (int ip = 0; ip < 4; ip++) {
        float2 lo_hi[4];
        #pragma unroll
        for (int j = 0; j < 4; j++)
            lo_hi[j] = *reinterpret_cast<float2*>(&acc2[ip][j]);
        #pragma unroll
        for (int half = 0; half < 2; half++) {
            int m  = tr * 8 + 2 * ip + half;
            int gm = m0 + m;
            if (gm < N_NODES) {
                float4 o;
                float accs[4] = {
                    (half ? lo_hi[0].y : lo_hi[0].x) + bv.x,
                    (half ? lo_hi[1].y : lo_hi[1].x) + bv.y,
                    (half ? lo_hi[2].y : lo_hi[2].x) + bv.z,
                    (half ? lo_hi[3].y : lo_hi[3].x) + bv.w };
                float* po = (float*)&o;
                #pragma unroll
                for (int j = 0; j < 4; j++) {
                    int d = tc * 4 + j;
                    float gate = 1.f / (1.f + __expf(-accs[j]));
                    float idf = As[d * 132 + m];
                    float tf  = As[(64 + d) * 132 + m];
                    po[j] = gate * idf + (1.f - gate) * tf;
                }
                *(float4*)(out + (size_t)gm * 64 + tc * 4) = o;
            }
        }
    }
}

// ---------------------------------------------------------------------------
// Launch: dual-chain pipeline.
//   side: fork -> CSR(zero,hist,scan,scatter) -> [wait prep] -> id1 -> id2
//   main: prep -> gemm -> [wait CSR] -> tx1 -> tx2 -> [wait id chain] -> fuse
// ---------------------------------------------------------------------------
extern "C" void kernel_launch(void* const* d_in, const int* in_sizes, int n_in,
                              void* d_out, int out_size) {
    const float* text_feats = (const float*)d_in[0];
    const int*   edge_row   = (const int*)d_in[1];
    const int*   edge_col   = (const int*)d_in[2];
    const float* edge_val   = (const float*)d_in[3];
    const int*   tail_mask  = (const int*)d_in[4];
    const float* user_emb   = (const float*)d_in[5];
    const float* item_emb   = (const float*)d_in[6];
    const float* W_text     = (const float*)d_in[7];
    const float* b_text     = (const float*)d_in[8];
    const float* W_fuse     = (const float*)d_in[9];
    const float* b_fuse     = (const float*)d_in[10];
    const float* tail_amp   = (const float*)d_in[11];
    float*       out        = (float*)d_out;

    const int n_edges = in_sizes[1];

    unsigned *p_id0, *p_tx0, *p_id1, *p_tx1, *p_id2, *p_tx2;
    cudaGetSymbolAddress((void**)&p_id0, g_id0h);
    cudaGetSymbolAddress((void**)&p_tx0, g_tx0h);
    cudaGetSymbolAddress((void**)&p_id1, g_id1h);
    cudaGetSymbolAddress((void**)&p_tx1, g_tx1h);
    cudaGetSymbolAddress((void**)&p_id2, g_id2h);
    cudaGetSymbolAddress((void**)&p_tx2, g_tx2h);

    static cudaStream_t s_side = nullptr;
    static cudaEvent_t  ev_fork = nullptr, ev_prep = nullptr,
                        ev_csr = nullptr, ev_id = nullptr;
    if (s_side == nullptr) {
        cudaStreamCreateWithFlags(&s_side, cudaStreamNonBlocking);
        cudaEventCreateWithFlags(&ev_fork, cudaEventDisableTiming);
        cudaEventCreateWithFlags(&ev_prep, cudaEventDisableTiming);
        cudaEventCreateWithFlags(&ev_csr,  cudaEventDisableTiming);
        cudaEventCreateWithFlags(&ev_id,   cudaEventDisableTiming);
        cudaFuncSetAttribute(fuse_gemm_kernel,
                             cudaFuncAttributeMaxDynamicSharedMemorySize,
                             FUSE_SMEM);
    }

    const int spmm_blocks = (N_NODES * 32 + 255) / 256;

    // --- main: prep (id0 fp16), then signal ---
    {
        int n4 = N64 / 4;
        prep_kernel<<<(n4 + 255) / 256, 256>>>(user_emb, item_emb);
    }
    cudaEventRecord(ev_prep, 0);
    cudaEventRecord(ev_fork, 0);

    // --- side: CSR build (self-contained), then id chain ---
    cudaStreamWaitEvent(s_side, ev_fork, 0);
    zero_cnt_kernel<<<(N_NODES / 4 + 255) / 256, 256, 0, s_side>>>();
    hist_kernel<<<(n_edges + 255) / 256, 256, 0, s_side>>>(edge_row, n_edges);
    scan_kernel<<<1, 1024, 0, s_side>>>();
    {
        int threads_needed = (n_edges + 3) / 4;
        scatter_kernel<<<(threads_needed + 255) / 256, 256, 0, s_side>>>(
            edge_row, edge_col, edge_val, n_edges);
    }
    cudaEventRecord(ev_csr, s_side);
    // id chain (needs prep, already waited via ev_fork ordering after prep)
    spmm_half_kernel<<<spmm_blocks, 256, 0, s_side>>>(p_id0, p_id1);
    spmm_half_kernel<<<spmm_blocks, 256, 0, s_side>>>(p_id1, p_id2);
    cudaEventRecord(ev_id, s_side);

    // --- main: text GEMM, then tx chain ---
    gemm_text_kernel<<<(N_NODES + 127) / 128, 256>>>(text_feats, W_text, b_text);
    cudaStreamWaitEvent(0, ev_csr, 0);
    spmm_half_kernel<<<spmm_blocks, 256>>>(p_tx0, p_tx1);
    spmm_half_kernel<<<spmm_blocks, 256>>>(p_tx1, p_tx2);

    // --- join id chain, fuse ---
    cudaStreamWaitEvent(0, ev_id, 0);
    fuse_gemm_kernel<<<(N_NODES + 127) / 128, 256, FUSE_SMEM>>>(
        user_emb, item_emb, tail_mask, W_fuse, b_fuse, tail_amp, out);
}

// round 10
// speedup vs baseline: 1.3840x; 1.3840x over previous
#include <cuda_runtime.h>
#include <cuda_bf16.h>
#include <cuda_fp16.h>
#include <cstdint>

#define NUM_USERS 100000
#define NUM_ITEMS 50000
#define N_NODES   150000
#define EMB_DIM   64
#define TEXT_DIM  384
#define N64 (N_NODES * EMB_DIM)
#define MAX_EDGES 5000000
#define SCAN_BLOCKS 147           // 147 * 1024 = 150528 >= N_NODES

// fp32 text projection (exact, used in fusion sums)
__device__ float g_text0[N64];

// fp16 interleaved buffers: per node 64 uint words:
//   uint4 q of a node = (id pair 2q, tx pair 2q, id pair 2q+1, tx pair 2q+1)
__device__ unsigned g_b0[N_NODES * 64];
__device__ unsigned g_b1[N_NODES * 64];
__device__ unsigned g_b2[N_NODES * 64];

// CSR machinery
__device__ int  g_cnt[N_NODES];
__device__ int  g_ofs[N_NODES + 1];
__device__ int  g_cur[N_NODES];
__device__ int  g_bsum[SCAN_BLOCKS];
__device__ int  g_boff[SCAN_BLOCKS];
__device__ int2 g_edges[MAX_EDGES];   // (col, val bits), row-sorted

static __device__ __forceinline__ unsigned pack_h2(float a, float b) {
    __half2 h = __floats2half2_rn(a, b);
    return *reinterpret_cast<unsigned*>(&h);
}
static __device__ __forceinline__ float2 unpack_h2(unsigned w) {
    return __half22float2(*reinterpret_cast<__half2*>(&w));
}

// ---------------------------------------------------------------------------
// Prep (main stream): fp16 id words of g_b0 from concat(uemb,iemb).
// ---------------------------------------------------------------------------
__global__ void prep_kernel(const float* __restrict__ uemb,
                            const float* __restrict__ iemb) {
    int i = blockIdx.x * blockDim.x + threadIdx.x;
    const int n4 = N64 / 4;
    const int u4 = NUM_USERS * (EMB_DIM / 4);
    if (i < n4) {
        float4 src = (i < u4) ? ((const float4*)uemb)[i]
                              : ((const float4*)iemb)[i - u4];
        g_b0[4 * i]     = pack_h2(src.x, src.y);
        g_b0[4 * i + 2] = pack_h2(src.z, src.w);
    }
}

// ---------------------------------------------------------------------------
// CSR build (side stream): zero, histogram, 3-phase parallel scan, scatter
// ---------------------------------------------------------------------------
__global__ void zero_cnt_kernel() {
    int i = blockIdx.x * blockDim.x + threadIdx.x;
    if (i < N_NODES / 4)
        ((int4*)g_cnt)[i] = make_int4(0, 0, 0, 0);
}

__global__ void hist_kernel(const int* __restrict__ erow, int n_edges) {
    int i = blockIdx.x * blockDim.x + threadIdx.x;
    if (i < n_edges) atomicAdd(&g_cnt[__ldg(erow + i)], 1);
}

// Phase 1: per-block (1024 nodes) exclusive scan -> g_ofs local; totals -> g_bsum
__global__ __launch_bounds__(1024)
void scan1_kernel() {
    __shared__ int sdata[1024];
    const int t = threadIdx.x;
    const int i = blockIdx.x * 1024 + t;
    int c = (i < N_NODES) ? g_cnt[i] : 0;
    sdata[t] = c;
    __syncthreads();
    #pragma unroll
    for (int off = 1; off < 1024; off <<= 1) {
        int v = (t >= off) ? sdata[t - off] : 0;
        __syncthreads();
        sdata[t] += v;
        __syncthreads();
    }
    if (i < N_NODES) g_ofs[i] = sdata[t] - c;   // exclusive local prefix
    if (t == 1023) g_bsum[blockIdx.x] = sdata[1023];
}

// Phase 2: single small block scans the 147 block sums -> g_boff (exclusive)
__global__ __launch_bounds__(256)
void scan2_kernel() {
    __shared__ int sdata[256];
    const int t = threadIdx.x;
    int c = (t < SCAN_BLOCKS) ? g_bsum[t] : 0;
    sdata[t] = c;
    __syncthreads();
    #pragma unroll
    for (int off = 1; off < 256; off <<= 1) {
        int v = (t >= off) ? sdata[t - off] : 0;
        __syncthreads();
        sdata[t] += v;
        __syncthreads();
    }
    if (t < SCAN_BLOCKS) g_boff[t] = sdata[t] - c;
    if (t == SCAN_BLOCKS - 1) g_ofs[N_NODES] = sdata[t];
}

// Phase 3: add block offsets, copy cursor
__global__ __launch_bounds__(1024)
void scan3_kernel() {
    const int i = blockIdx.x * 1024 + threadIdx.x;
    if (i < N_NODES) {
        int v = g_ofs[i] + g_boff[blockIdx.x];
        g_ofs[i] = v;
        g_cur[i] = v;
    }
}

__global__ void scatter_kernel(const int*   __restrict__ erow,
                               const int*   __restrict__ ecol,
                               const float* __restrict__ eval,
                               int n_edges) {
    int base = (blockIdx.x * blockDim.x + threadIdx.x) * 4;
    #pragma unroll
    for (int j = 0; j < 4; j++) {
        int i = base + j;
        if (i < n_edges) {
            int r = __ldg(erow + i);
            int pos = atomicAdd(&g_cur[r], 1);
            g_edges[pos] = make_int2(__ldg(ecol + i),
                                     __float_as_int(__ldg(eval + i)));
        }
    }
}

// ---------------------------------------------------------------------------
// Text GEMM (packed f32x2 FFMA). Writes fp32 g_text0 + fp16 tx words of g_b0.
// ---------------------------------------------------------------------------
__global__ void gemm_text_kernel(const float* __restrict__ A,
                                 const float* __restrict__ W,
                                 const float* __restrict__ bias) {
    __shared__ float As[16][132];
    __shared__ float Bs[16][64];

    const int tid = threadIdx.x;
    const int m0  = blockIdx.x * 128;
    const int tr  = tid >> 4;
    const int tc  = tid & 15;

    unsigned long long acc2[4][4];
    #pragma unroll
    for (int ip = 0; ip < 4; ip++)
        #pragma unroll
        for (int j = 0; j < 4; j++) acc2[ip][j] = 0ull;

    for (int k0 = 0; k0 < TEXT_DIM; k0 += 16) {
        #pragma unroll
        for (int p = 0; p < 2; p++) {
            int idx = tid + p * 256;
            int m   = idx >> 2;
            int kq  = idx & 3;
            float4 a4 = make_float4(0.f, 0.f, 0.f, 0.f);
            int gm = m0 + m;
            if (gm < N_NODES)
                a4 = *(const float4*)(A + (size_t)gm * TEXT_DIM + k0 + kq * 4);
            As[kq * 4 + 0][m] = a4.x;
            As[kq * 4 + 1][m] = a4.y;
            As[kq * 4 + 2][m] = a4.z;
            As[kq * 4 + 3][m] = a4.w;
        }
        {
            int k  = tid >> 4;
            int nq = tid & 15;
            float4 b4 = *(const float4*)(W + (size_t)(k0 + k) * 64 + nq * 4);
            *(float4*)&Bs[k][nq * 4] = b4;
        }
        __syncthreads();

        #pragma unroll
        for (int k = 0; k < 16; k++) {
            const unsigned long long* pa =
                (const unsigned long long*)&As[k][tr * 8];
            unsigned long long av[4] = {pa[0], pa[1], pa[2], pa[3]};
            float4 b = *(const float4*)&Bs[k][tc * 4];
            unsigned long long bd[4];
            asm("mov.b64 %0, {%1, %1};" : "=l"(bd[0]) : "r"(__float_as_uint(b.x)));
            asm("mov.b64 %0, {%1, %1};" : "=l"(bd[1]) : "r"(__float_as_uint(b.y)));
            asm("mov.b64 %0, {%1, %1};" : "=l"(bd[2]) : "r"(__float_as_uint(b.z)));
            asm("mov.b64 %0, {%1, %1};" : "=l"(bd[3]) : "r"(__float_as_uint(b.w)));
            #pragma unroll
            for (int ip = 0; ip < 4; ip++)
                #pragma unroll
                for (int j = 0; j < 4; j++)
                    asm("fma.rn.f32x2 %0, %1, %2, %3;"
                        : "=l"(acc2[ip][j])
                        : "l"(av[ip]), "l"(bd[j]), "l"(acc2[ip][j]));
        }
        __syncthreads();
    }

    float4 bv = *(const float4*)(bias + tc * 4);
    #pragma unroll
    for (int ip = 0; ip < 4; ip++) {
        float2 lo_hi[4];
        #pragma unroll
        for (int j = 0; j < 4; j++)
            lo_hi[j] = *reinterpret_cast<float2*>(&acc2[ip][j]);
        #pragma unroll
        for (int half = 0; half < 2; half++) {
            int gm = m0 + tr * 8 + 2 * ip + half;
            if (gm < N_NODES) {
                float4 o;
                o.x = (half ? lo_hi[0].y : lo_hi[0].x) + bv.x;
                o.y = (half ? lo_hi[1].y : lo_hi[1].x) + bv.y;
                o.z = (half ? lo_hi[2].y : lo_hi[2].x) + bv.z;
                o.w = (half ? lo_hi[3].y : lo_hi[3].x) + bv.w;
                *(float4*)(g_text0 + (size_t)gm * 64 + tc * 4) = o;
                g_b0[(size_t)gm * 64 + 4 * tc + 1] = pack_h2(o.x, o.y);
                g_b0[(size_t)gm * 64 + 4 * tc + 3] = pack_h2(o.z, o.w);
            }
        }
    }
}

// ---------------------------------------------------------------------------
// CSR SpMM (round-8 layout) + software-pipelined edge descriptors.
// Warp per row; half-warps take even/odd edges; LDG.128 gathers serve both
// streams; edge int2s for the NEXT iteration load while current gathers fly.
// ---------------------------------------------------------------------------
#define SPMM_FMA(W, V)                                                        \
    do {                                                                      \
        float2 _f;                                                            \
        _f = unpack_h2((W).x); aid0.x += _f.x * (V); aid0.y += _f.y * (V);    \
        _f = unpack_h2((W).y); atx0.x += _f.x * (V); atx0.y += _f.y * (V);    \
        _f = unpack_h2((W).z); aid1.x += _f.x * (V); aid1.y += _f.y * (V);    \
        _f = unpack_h2((W).w); atx1.x += _f.x * (V); atx1.y += _f.y * (V);    \
    } while (0)

__global__ void spmm_csr_kernel(const unsigned* __restrict__ src_b,
                                unsigned* __restrict__ dst_b) {
    int row  = (blockIdx.x * blockDim.x + threadIdx.x) >> 5;
    int lane = threadIdx.x & 31;
    if (row >= N_NODES) return;

    const int h = lane >> 4;       // edge parity
    const int l = lane & 15;       // uint4 index within node vector

    int beg = __ldg(&g_ofs[row]);
    int end = __ldg(&g_ofs[row + 1]);
    int cnt = end - beg;
    int nfull = cnt >> 3;          // iterations of 8 edges (4 per half-warp)

    const uint4* src = (const uint4*)src_b;   // node*16 + l

    float2 aid0 = make_float2(0.f, 0.f), atx0 = make_float2(0.f, 0.f);
    float2 aid1 = make_float2(0.f, 0.f), atx1 = make_float2(0.f, 0.f);

    int e = beg + h;
    int2 d0, d1, d2, d3;
    if (nfull > 0) {               // prologue: first batch of edge descriptors
        d0 = __ldg(&g_edges[e]);
        d1 = __ldg(&g_edges[e + 2]);
        d2 = __ldg(&g_edges[e + 4]);
        d3 = __ldg(&g_edges[e + 6]);
    }
    for (int it = 0; it < nfull; it++) {
        // issue gathers for current batch
        uint4 w0 = __ldg(src + (size_t)d0.x * 16 + l);
        uint4 w1 = __ldg(src + (size_t)d1.x * 16 + l);
        uint4 w2 = __ldg(src + (size_t)d2.x * 16 + l);
        uint4 w3 = __ldg(src + (size_t)d3.x * 16 + l);
        float v0 = __int_as_float(d0.y);
        float v1 = __int_as_float(d1.y);
        float v2 = __int_as_float(d2.y);
        float v3 = __int_as_float(d3.y);
        // prefetch next batch descriptors (overlaps with gather latency)
        if (it + 1 < nfull) {
            e += 8;
            d0 = __ldg(&g_edges[e]);
            d1 = __ldg(&g_edges[e + 2]);
            d2 = __ldg(&g_edges[e + 4]);
            d3 = __ldg(&g_edges[e + 6]);
        } else {
            e += 8;
        }
        SPMM_FMA(w0, v0);
        SPMM_FMA(w1, v1);
        SPMM_FMA(w2, v2);
        SPMM_FMA(w3, v3);
    }
    while (e < end) {              // tail, <= 7 edges total
        int2 d = __ldg(&g_edges[e]);
        uint4 w = __ldg(src + (size_t)d.x * 16 + l);
        float v = __int_as_float(d.y);
        SPMM_FMA(w, v);
        e += 2;
    }

    // combine even/odd halves
    aid0.x += __shfl_xor_sync(0xffffffffu, aid0.x, 16);
    aid0.y += __shfl_xor_sync(0xffffffffu, aid0.y, 16);
    atx0.x += __shfl_xor_sync(0xffffffffu, atx0.x, 16);
    atx0.y += __shfl_xor_sync(0xffffffffu, atx0.y, 16);
    aid1.x += __shfl_xor_sync(0xffffffffu, aid1.x, 16);
    aid1.y += __shfl_xor_sync(0xffffffffu, aid1.y, 16);
    atx1.x += __shfl_xor_sync(0xffffffffu, atx1.x, 16);
    atx1.y += __shfl_xor_sync(0xffffffffu, atx1.y, 16);

    if (h == 0) {
        uint4 w;
        w.x = pack_h2(aid0.x, aid0.y);
        w.y = pack_h2(atx0.x, atx0.y);
        w.z = pack_h2(aid1.x, aid1.y);
        w.w = pack_h2(atx1.x, atx1.y);
        ((uint4*)dst_b)[(size_t)row * 16 + l] = w;
    }
}

// ---------------------------------------------------------------------------
// Fusion as register-blocked GEMM (M=150K, K=128, N=64) + gate epilogue.
// ---------------------------------------------------------------------------
#define FUSE_SMEM (128 * 132 * 4 + 128 * 64 * 4)
__global__ __launch_bounds__(256)
void fuse_gemm_kernel(const float* __restrict__ uemb,
                      const float* __restrict__ iemb,
                      const int*   __restrict__ tail_mask,
                      const float* __restrict__ W_fuse,
                      const float* __restrict__ b_fuse,
                      const float* __restrict__ tail_amp,
                      float* __restrict__ out) {
    extern __shared__ float sm[];
    float* As = sm;                 // [128][132] k-major
    float* Bs = sm + 128 * 132;     // [128][64]

    const int tid = threadIdx.x;
    const int m0  = blockIdx.x * 128;

    #pragma unroll
    for (int p = 0; p < 8; p++) {
        int i = tid + p * 256;
        ((float4*)Bs)[i] = ((const float4*)W_fuse)[i];
    }

    const float amp = 1.f + 1.f / (1.f + __expf(-tail_amp[0]));

    {
        int n    = tid >> 1;
        int node = m0 + n;
        int sub  = tid & 1;
        bool valid = node < N_NODES;
        int nc = valid ? node : 0;
        const float2* id0p = (nc < NUM_USERS)
            ? (const float2*)(uemb + (size_t)nc * 64)
            : (const float2*)(iemb + (size_t)(nc - NUM_USERS) * 64);
        const float2* t0p = (const float2*)(g_text0 + (size_t)nc * 64);
        const uint2*  b1p = (const uint2*)g_b1 + (size_t)nc * 32;
        const uint2*  b2p = (const uint2*)g_b2 + (size_t)nc * 32;
        const float third = 1.f / 3.f;
        float tmul = (valid && __ldg(tail_mask + nc) != 0) ? amp * third : third;
        #pragma unroll 4
        for (int p = 0; p < 16; p++) {
            int pp = sub * 16 + p;
            float2 i0 = valid ? __ldg(id0p + pp) : make_float2(0.f, 0.f);
            float2 t0 = valid ? __ldg(t0p + pp)  : make_float2(0.f, 0.f);
            uint2 w1 = valid ? __ldg(b1p + pp) : make_uint2(0u, 0u);
            uint2 w2 = valid ? __ldg(b2p + pp) : make_uint2(0u, 0u);
            float2 l1i = unpack_h2(w1.x), l1t = unpack_h2(w1.y);
            float2 l2i = unpack_h2(w2.x), l2t = unpack_h2(w2.y);
            int d = 2 * pp;
            As[(d + 0) * 132 + n]      = (i0.x + l1i.x + l2i.x) * third;
            As[(d + 1) * 132 + n]      = (i0.y + l1i.y + l2i.y) * third;
            As[(64 + d + 0) * 132 + n] = (t0.x + l1t.x + l2t.x) * tmul;
            As[(64 + d + 1) * 132 + n] = (t0.y + l1t.y + l2t.y) * tmul;
        }
    }
    __syncthreads();

    const int tr = tid >> 4;
    const int tc = tid & 15;

    unsigned long long acc2[4][4];
    #pragma unroll
    for (int ip = 0; ip < 4; ip++)
        #pragma unroll
        for (int j = 0; j < 4; j++) acc2[ip][j] = 0ull;

    #pragma unroll 4
    for (int k = 0; k < 128; k++) {
        const unsigned long long* pa =
            (const unsigned long long*)(As + k * 132 + tr * 8);
        unsigned long long av[4] = {pa[0], pa[1], pa[2], pa[3]};
        float4 b = *(const float4*)(Bs + k * 64 + tc * 4);
        unsigned long long bd[4];
        asm("mov.b64 %0, {%1, %1};" : "=l"(bd[0]) : "r"(__float_as_uint(b.x)));
        asm("mov.b64 %0, {%1, %1};" : "=l"(bd[1]) : "r"(__float_as_uint(b.y)));
        asm("mov.b64 %0, {%1, %1};" : "=l"(bd[2]) : "r"(__float_as_uint(b.z)));
        asm("mov.b64 %0, {%1, %1};" : "=l"(bd[3]) : "r"(__float_as_uint(b.w)));
        #pragma unroll
        for (int ip = 0; ip < 4; ip++)
            #pragma unroll
            for (int j = 0; j < 4; j++)
                asm("fma.rn.f32x2 %0, %1, %2, %3;"
                    : "=l"(acc2[ip][j])
                    : "l"(av[ip]), "l"(bd[j]), "l"(acc2[ip][j]));
    }

    float4 bv = *(const float4*)(b_fuse + tc * 4);
    #pragma unroll
    for (int ip = 0; ip < 4; ip++) {
        float2 lo_hi[4];
        #pragma unroll
        for (int j = 0; j < 4; j++)
            lo_hi[j] = *reinterpret_cast<float2*>(&acc2[ip][j]);
        #pragma unroll
        for (int half = 0; half < 2; half++) {
            int m  = tr * 8 + 2 * ip + half;
            int gm = m0 + m;
            if (gm < N_NODES) {
                float4 o;
                float accs[4] = {
                    (half ? lo_hi[0].y : lo_hi[0].x) + bv.x,
                    (half ? lo_hi[1].y : lo_hi[1].x) + bv.y,
                    (half ? lo_hi[2].y : lo_hi[2].x) + bv.z,
                    (half ? lo_hi[3].y : lo_hi[3].x) + bv.w };
                float* po = (float*)&o;
                #pragma unroll
                for (int j = 0; j < 4; j++) {
                    int d = tc * 4 + j;
                    float gate = 1.f / (1.f + __expf(-accs[j]));
                    float idf = As[d * 132 + m];
                    float tf  = As[(64 + d) * 132 + m];
                    po[j] = gate * idf + (1.f - gate) * tf;
                }
                *(float4*)(out + (size_t)gm * 64 + tc * 4) = o;
            }
        }
    }
}

// ---------------------------------------------------------------------------
// Launch (round-8 schedule): fork side stream with self-contained CSR chain
// (zero -> hist -> scan1/2/3 -> scatter) while main does prep + GEMM.
// Join before spmm.
// ---------------------------------------------------------------------------
extern "C" void kernel_launch(void* const* d_in, const int* in_sizes, int n_in,
                              void* d_out, int out_size) {
    const float* text_feats = (const float*)d_in[0];
    const int*   edge_row   = (const int*)d_in[1];
    const int*   edge_col   = (const int*)d_in[2];
    const float* edge_val   = (const float*)d_in[3];
    const int*   tail_mask  = (const int*)d_in[4];
    const float* user_emb   = (const float*)d_in[5];
    const float* item_emb   = (const float*)d_in[6];
    const float* W_text     = (const float*)d_in[7];
    const float* b_text     = (const float*)d_in[8];
    const float* W_fuse     = (const float*)d_in[9];
    const float* b_fuse     = (const float*)d_in[10];
    const float* tail_amp   = (const float*)d_in[11];
    float*       out        = (float*)d_out;

    const int n_edges = in_sizes[1];

    unsigned *p_b0, *p_b1, *p_b2;
    cudaGetSymbolAddress((void**)&p_b0, g_b0);
    cudaGetSymbolAddress((void**)&p_b1, g_b1);
    cudaGetSymbolAddress((void**)&p_b2, g_b2);

    static cudaStream_t s_side = nullptr;
    static cudaEvent_t  ev_fork = nullptr, ev_side = nullptr;
    if (s_side == nullptr) {
        cudaStreamCreateWithFlags(&s_side, cudaStreamNonBlocking);
        cudaEventCreateWithFlags(&ev_fork, cudaEventDisableTiming);
        cudaEventCreateWithFlags(&ev_side, cudaEventDisableTiming);
        cudaFuncSetAttribute(fuse_gemm_kernel,
                             cudaFuncAttributeMaxDynamicSharedMemorySize,
                             FUSE_SMEM);
    }

    // Fork: self-contained CSR build on the side stream
    cudaEventRecord(ev_fork, 0);
    cudaStreamWaitEvent(s_side, ev_fork, 0);
    zero_cnt_kernel<<<(N_NODES / 4 + 255) / 256, 256, 0, s_side>>>();
    hist_kernel<<<(n_edges + 255) / 256, 256, 0, s_side>>>(edge_row, n_edges);
    scan1_kernel<<<SCAN_BLOCKS, 1024, 0, s_side>>>();
    scan2_kernel<<<1, 256, 0, s_side>>>();
    scan3_kernel<<<SCAN_BLOCKS, 1024, 0, s_side>>>();
    {
        int threads_needed = (n_edges + 3) / 4;
        scatter_kernel<<<(threads_needed + 255) / 256, 256, 0, s_side>>>(
            edge_row, edge_col, edge_val, n_edges);
    }
    cudaEventRecord(ev_side, s_side);

    // Main stream: prep + text GEMM
    {
        int n4 = N64 / 4;
        prep_kernel<<<(n4 + 255) / 256, 256>>>(user_emb, item_emb);
    }
    gemm_text_kernel<<<(N_NODES + 127) / 128, 256>>>(text_feats, W_text, b_text);

    // Join, then propagate
    cudaStreamWaitEvent(0, ev_side, 0);
    {
        int blocks = (N_NODES * 32 + 255) / 256;
        spmm_csr_kernel<<<blocks, 256>>>(p_b0, p_b1);
        spmm_csr_kernel<<<blocks, 256>>>(p_b1, p_b2);
    }
    // Fusion epilogue
    fuse_gemm_kernel<<<(N_NODES + 127) / 128, 256, FUSE_SMEM>>>(
        user_emb, item_emb, tail_mask, W_fuse, b_fuse, tail_amp, out);
}